// round 1
// baseline (speedup 1.0000x reference)
#include <cuda_runtime.h>
#include <math.h>

#define D    16
#define KNN  16
#define FULL 0xffffffffu

#define NMAX 30720
#define MMAX 8192

// ---- scratch (static device globals; no allocation in kernel_launch) ----
__device__ float4 g_atoms[MMAX];            // x,y,z,||y||^2  (padded tail = huge norm)
__device__ float  g_t[MMAX * D];            // transformed atom features
__device__ int    g_idx[NMAX * KNN];        // knn indices
__device__ float  g_rinv[NMAX * KNN];       // 1/dist^2 feature
__device__ float  g_h1[NMAX * KNN * D];     // leaky(conv1) pre-BN
__device__ float  g_h2[NMAX * KNN * D];     // leaky(conv2) pre-BN
__device__ float  g_fx1[NMAX * D];          // pooled branch-1 features
__device__ float  g_part1[2048 * 32];       // block partials: sum[16], sumsq[16]
__device__ float  g_part2[512 * 32];
__device__ float  g_bn[64];                 // sc1[16] sh1[16] sc2[16] sh2[16]

__device__ __forceinline__ float leaky(float a) { return a > 0.f ? a : 0.2f * a; }

// ---------------------------------------------------------------------------
// K0: atom prep — 3-layer MLP on atom features + pack coords with norms
// ---------------------------------------------------------------------------
__global__ void prep_kernel(const float* __restrict__ atom_xyz,
                            const float* __restrict__ atom_types,
                            const float* __restrict__ Wt1, const float* __restrict__ bt1,
                            const float* __restrict__ Wt2, const float* __restrict__ bt2,
                            const float* __restrict__ Wt3, const float* __restrict__ bt3,
                            int M, int Mpad)
{
    __shared__ float sW[3][D * D];
    __shared__ float sB[3][D];
    int tid = threadIdx.x;
    for (int i = tid; i < D * D; i += blockDim.x) {
        sW[0][i] = Wt1[i];
        sW[1][i] = Wt2[i];
        sW[2][i] = Wt3[i];
    }
    if (tid < D) { sB[0][tid] = bt1[tid]; sB[1][tid] = bt2[tid]; sB[2][tid] = bt3[tid]; }
    __syncthreads();

    int i = blockIdx.x * blockDim.x + tid;
    if (i >= Mpad) return;
    if (i >= M) {  // pad: never selected by knn
        g_atoms[i] = make_float4(0.f, 0.f, 0.f, 3.0e38f);
        return;
    }
    float x = atom_xyz[i * 3 + 0], y = atom_xyz[i * 3 + 1], z = atom_xyz[i * 3 + 2];
    g_atoms[i] = make_float4(x, y, z, x * x + y * y + z * z);

    float v[D], u[D];
#pragma unroll
    for (int j = 0; j < D; j++) v[j] = atom_types[i * D + j];
#pragma unroll
    for (int l = 0; l < 3; l++) {
#pragma unroll
        for (int j = 0; j < D; j++) {
            float a = sB[l][j];
#pragma unroll
            for (int kk = 0; kk < D; kk++) a = fmaf(v[kk], sW[l][kk * D + j], a);
            u[j] = leaky(a);
        }
#pragma unroll
        for (int j = 0; j < D; j++) v[j] = u[j];
    }
#pragma unroll
    for (int j = 0; j < D; j++) g_t[i * D + j] = v[j];
}

// ---------------------------------------------------------------------------
// K1: kNN — one warp per point. Warp-collective sorted top-16 across lanes
// 0..15 (lanes 16..31 hold +inf sentinels), packed as
// (monotonic(dist_bits) << 32) | atom_idx  so ties break by lower index,
// matching jax.lax.top_k.
// ---------------------------------------------------------------------------
__global__ void knn_kernel(const float* __restrict__ xyz, int N, int M)
{
    int gw   = (blockIdx.x * blockDim.x + threadIdx.x) >> 5;
    int lane = threadIdx.x & 31;
    if (gw >= N) return;

    const float px = xyz[gw * 3 + 0], py = xyz[gw * 3 + 1], pz = xyz[gw * 3 + 2];
    const float cx = -2.f * px, cy = -2.f * py, cz = -2.f * pz;

    unsigned long long lst = ~0ULL;   // per-lane slot of the sorted list
    unsigned long long tau = ~0ULL;   // current 16th-best (lane 15's value)

    int Mpad = (M + 31) & ~31;
    for (int base = lane; base < Mpad; base += 32) {
        float4 a = g_atoms[base];
        // s = ||y||^2 - 2 x·y   (ordering-equivalent to squared distance)
        float s = fmaf(cx, a.x, a.w);
        s = fmaf(cy, a.y, s);
        s = fmaf(cz, a.z, s);
        // monotonic float->uint mapping (handles negative s from rounding)
        unsigned u = __float_as_uint(s);
        u ^= ((unsigned)((int)u >> 31)) | 0x80000000u;
        unsigned long long c = ((unsigned long long)u << 32) | (unsigned)base;

        unsigned ball = __ballot_sync(FULL, c < tau);
        while (ball) {
            int src = __ffs(ball) - 1;
            ball &= ball - 1;
            unsigned long long cc = __shfl_sync(FULL, c, src);
            if (cc < tau) {   // uniform branch (cc, tau warp-uniform)
                unsigned long long up = __shfl_up_sync(FULL, lst, 1);
                bool gt = lst > cc;
                unsigned gmask = __ballot_sync(FULL, gt);
                int pos = __ffs(gmask) - 1;
                if (gt) lst = (lane == pos) ? cc : up;
                tau = __shfl_sync(FULL, lst, 15);
            }
        }
    }

    if (lane < KNN) {
        int ai = (int)(unsigned)(lst & 0xffffffffu);
        float4 a = g_atoms[ai];
        float dx = px - a.x, dy = py - a.y, dz = pz - a.z;
        float dd = fmaf(dz, dz, fmaf(dy, dy, dx * dx));  // exact recomputed dist^2
        g_idx[gw * KNN + lane]  = ai;
        g_rinv[gw * KNN + lane] = 1.0f / dd;
    }
}

// ---------------------------------------------------------------------------
// K2: pass A — per (point,k) row: feat=[t[idx], 1/d2] -> conv1 -> leaky.
// Store h1, emit deterministic block partial sums/sumsq for BN1.
// ---------------------------------------------------------------------------
__global__ void passA_kernel(const float* __restrict__ W1, const float* __restrict__ b1,
                             int NR)
{
    __shared__ float sW[(D + 1) * D];
    __shared__ float sb[D];
    __shared__ float red[8 * 32];
    int tid = threadIdx.x;
    for (int i = tid; i < (D + 1) * D; i += blockDim.x) sW[i] = W1[i];
    if (tid < D) sb[tid] = b1[tid];
    __syncthreads();

    int r = blockIdx.x * blockDim.x + tid;
    float h[D];
#pragma unroll
    for (int j = 0; j < D; j++) h[j] = 0.f;

    if (r < NR) {
        int   ai = g_idx[r];
        float rv = g_rinv[r];
        float f[D];
#pragma unroll
        for (int j = 0; j < D; j++) f[j] = g_t[ai * D + j];
#pragma unroll
        for (int j = 0; j < D; j++) {
            float a = sb[j];
#pragma unroll
            for (int kk = 0; kk < D; kk++) a = fmaf(f[kk], sW[kk * D + j], a);
            a = fmaf(rv, sW[D * D + j], a);
            h[j] = leaky(a);
        }
#pragma unroll
        for (int j = 0; j < D; j++) g_h1[r * D + j] = h[j];
    }

    int lane = tid & 31, w = tid >> 5;
#pragma unroll
    for (int j = 0; j < D; j++) {
        float sv = h[j], qv = h[j] * h[j];
#pragma unroll
        for (int o = 16; o > 0; o >>= 1) {
            sv += __shfl_xor_sync(FULL, sv, o);
            qv += __shfl_xor_sync(FULL, qv, o);
        }
        if (lane == 0) { red[w * 32 + j] = sv; red[w * 32 + 16 + j] = qv; }
    }
    __syncthreads();
    if (tid < 32) {
        float acc = 0.f;
#pragma unroll
        for (int ww = 0; ww < 8; ww++) acc += red[ww * 32 + tid];
        g_part1[blockIdx.x * 32 + tid] = acc;
    }
}

// ---------------------------------------------------------------------------
// K3/K5: BN finalize — reduce block partials, compute scale/shift
// ---------------------------------------------------------------------------
__global__ void bnfin_kernel(const float* __restrict__ gamma,
                             const float* __restrict__ beta,
                             int nb, float inv_n, int which)
{
    const float* part = which ? g_part2 : g_part1;
    __shared__ float sm[8][32];
    __shared__ float tot[32];
    int c = threadIdx.x & 31, sl = threadIdx.x >> 5;
    float a = 0.f;
    for (int b = sl; b < nb; b += 8) a += part[b * 32 + c];
    sm[sl][c] = a;
    __syncthreads();
    if (threadIdx.x < 32) {
        float t = 0.f;
#pragma unroll
        for (int w = 0; w < 8; w++) t += sm[w][threadIdx.x];
        tot[threadIdx.x] = t;
    }
    __syncthreads();
    if (threadIdx.x < 16) {
        int j = threadIdx.x;
        float mean = tot[j] * inv_n;
        float var  = tot[16 + j] * inv_n - mean * mean;
        float sc   = gamma[j] * rsqrtf(var + 1e-5f);
        float sh   = beta[j] - mean * sc;
        g_bn[which * 32 + j]      = sc;
        g_bn[which * 32 + 16 + j] = sh;
    }
}

// ---------------------------------------------------------------------------
// K4: pass B — per point: bn1(h1) -> fx1 sum-pool; conv2 -> leaky -> h2;
// BN2 partials.
// ---------------------------------------------------------------------------
__global__ void passB_kernel(const float* __restrict__ W2, const float* __restrict__ b2,
                             int N)
{
    __shared__ float sW[D * D], sb[D], ssc[D], ssh[D];
    __shared__ float red[4 * 32];
    int tid = threadIdx.x;
    for (int i = tid; i < D * D; i += blockDim.x) sW[i] = W2[i];
    if (tid < D) { sb[tid] = b2[tid]; ssc[tid] = g_bn[tid]; ssh[tid] = g_bn[16 + tid]; }
    __syncthreads();

    int i = blockIdx.x * blockDim.x + tid;
    float s[D], q[D];
#pragma unroll
    for (int j = 0; j < D; j++) { s[j] = 0.f; q[j] = 0.f; }

    if (i < N) {
        float fx[D];
#pragma unroll
        for (int j = 0; j < D; j++) fx[j] = 0.f;
        for (int k = 0; k < KNN; k++) {
            int row = (i * KNN + k) * D;
            float y[D];
#pragma unroll
            for (int j = 0; j < D; j++) {
                y[j] = fmaf(g_h1[row + j], ssc[j], ssh[j]);
                fx[j] += y[j];
            }
#pragma unroll
            for (int j = 0; j < D; j++) {
                float a = sb[j];
#pragma unroll
                for (int kk = 0; kk < D; kk++) a = fmaf(y[kk], sW[kk * D + j], a);
                a = leaky(a);
                g_h2[row + j] = a;
                s[j] += a;
                q[j] = fmaf(a, a, q[j]);
            }
        }
#pragma unroll
        for (int j = 0; j < D; j++) g_fx1[i * D + j] = fx[j];
    }

    int lane = tid & 31, w = tid >> 5;
#pragma unroll
    for (int j = 0; j < D; j++) {
        float sv = s[j], qv = q[j];
#pragma unroll
        for (int o = 16; o > 0; o >>= 1) {
            sv += __shfl_xor_sync(FULL, sv, o);
            qv += __shfl_xor_sync(FULL, qv, o);
        }
        if (lane == 0) { red[w * 32 + j] = sv; red[w * 32 + 16 + j] = qv; }
    }
    __syncthreads();
    if (tid < 32) {
        float acc = 0.f;
#pragma unroll
        for (int ww = 0; ww < 4; ww++) acc += red[ww * 32 + tid];
        g_part2[blockIdx.x * 32 + tid] = acc;
    }
}

// ---------------------------------------------------------------------------
// K6: pass C — per point: bn2(h2) -> fx2 sum-pool; out = [fx1,fx2] @ W3 + b3
// ---------------------------------------------------------------------------
__global__ void passC_kernel(const float* __restrict__ W3, const float* __restrict__ b3,
                             float* __restrict__ out, int N)
{
    __shared__ float sW[2 * D * D], sb[D], ssc[D], ssh[D];
    int tid = threadIdx.x;
    for (int i = tid; i < 2 * D * D; i += blockDim.x) sW[i] = W3[i];
    if (tid < D) { sb[tid] = b3[tid]; ssc[tid] = g_bn[32 + tid]; ssh[tid] = g_bn[48 + tid]; }
    __syncthreads();

    int i = blockIdx.x * blockDim.x + tid;
    if (i >= N) return;

    float fx2[D];
#pragma unroll
    for (int j = 0; j < D; j++) fx2[j] = 0.f;
    for (int k = 0; k < KNN; k++) {
        int row = (i * KNN + k) * D;
#pragma unroll
        for (int j = 0; j < D; j++)
            fx2[j] += fmaf(g_h2[row + j], ssc[j], ssh[j]);
    }
    float fx1[D];
#pragma unroll
    for (int j = 0; j < D; j++) fx1[j] = g_fx1[i * D + j];

#pragma unroll
    for (int j = 0; j < D; j++) {
        float a = sb[j];
#pragma unroll
        for (int kk = 0; kk < D; kk++) a = fmaf(fx1[kk], sW[kk * D + j], a);
#pragma unroll
        for (int kk = 0; kk < D; kk++) a = fmaf(fx2[kk], sW[(D + kk) * D + j], a);
        out[i * D + j] = a;
    }
}

// ---------------------------------------------------------------------------
extern "C" void kernel_launch(void* const* d_in, const int* in_sizes, int n_in,
                              void* d_out, int out_size)
{
    const float* xyz        = (const float*)d_in[0];
    const float* atom_xyz   = (const float*)d_in[1];
    const float* atom_types = (const float*)d_in[2];
    const float* Wt1 = (const float*)d_in[3];
    const float* bt1 = (const float*)d_in[4];
    const float* Wt2 = (const float*)d_in[5];
    const float* bt2 = (const float*)d_in[6];
    const float* Wt3 = (const float*)d_in[7];
    const float* bt3 = (const float*)d_in[8];
    const float* W1  = (const float*)d_in[9];
    const float* b1  = (const float*)d_in[10];
    const float* W2  = (const float*)d_in[11];
    const float* b2  = (const float*)d_in[12];
    const float* W3  = (const float*)d_in[13];
    const float* b3  = (const float*)d_in[14];
    const float* g1  = (const float*)d_in[15];
    const float* be1 = (const float*)d_in[16];
    const float* g2  = (const float*)d_in[17];
    const float* be2 = (const float*)d_in[18];

    int N = in_sizes[0] / 3;
    int M = in_sizes[1] / 3;
    int Mpad = (M + 31) & ~31;

    prep_kernel<<<(Mpad + 255) / 256, 256>>>(atom_xyz, atom_types,
                                             Wt1, bt1, Wt2, bt2, Wt3, bt3, M, Mpad);

    knn_kernel<<<(N * 32 + 255) / 256, 256>>>(xyz, N, M);

    int NR  = N * KNN;
    int nb1 = (NR + 255) / 256;
    passA_kernel<<<nb1, 256>>>(W1, b1, NR);

    bnfin_kernel<<<1, 256>>>(g1, be1, nb1, 1.0f / (float)NR, 0);

    int nb2 = (N + 127) / 128;
    passB_kernel<<<nb2, 128>>>(W2, b2, N);

    bnfin_kernel<<<1, 256>>>(g2, be2, nb2, 1.0f / (float)NR, 1);

    passC_kernel<<<nb2, 128>>>(W3, b3, (float*)d_out, N);
}